// round 14
// baseline (speedup 1.0000x reference)
#include <cuda_runtime.h>
#include <cuda_bf16.h>
#include <math.h>
#include <stdint.h>

// ---------------------------------------------------------------------------
// EdgeFeatureConvBlock  (B=32, N=1024, P=8192, K=16, C_IN=32, E_IN=4, OUT=64)
// R14: R13 base (best: 358us). Inner-loop B-fragment duplication identified:
//      4 cg-warps re-read the same X half-tile. For C<=64 layers switch to
//      2cg x 4mh warp split: each LDS.128 feeds 6 mma (was 3) -> CTA smem
//      reads halved. A-regs 2xNG -> occ 2 for those kernels. Layer-0 (C=68)
//      keeps the 4cg x 2mh path. Accumulation order unchanged.
// ---------------------------------------------------------------------------

#define BB   32
#define NN   1024
#define PP   8192
#define KK   16
#define CIN  32
#define EIN  4
#define O0   64
#define M_ALL (BB*NN*KK) // 524288
#define M_SC  (BB*NN)    // 32768
#define BN_EPS 1e-5f

// ------------------------- scratch (device globals) ------------------------
__device__ float g_S0[(size_t)O0 * M_ALL];   // [64][M]
__device__ float g_S1[(size_t)O0 * M_ALL];
__device__ float g_scb[(size_t)O0 * M_SC];
__device__ float g_featT[BB * NN * CIN];     // node-major features
__device__ int   g_topidx[M_ALL];
__device__ float g_eft[BB * EIN * NN * KK];
__device__ float g_sum[4][O0];
__device__ float g_sqsum[4][O0];
__device__ float g_a[4][O0];
__device__ float g_c[4][O0];
// W fragment tables: [64][NG][16 u16] permuted (hi groups then lo groups)
__device__ uint16_t g_wx0[64 * 10 * 16];     // layer0: C=68, NG=10
__device__ uint16_t g_wx1[64 * 8 * 16];      // layer1: C=64, NG=8
__device__ uint16_t g_wx2[64 * 8 * 16];      // layer2: C=64, NG=8
__device__ uint16_t g_wxsc[64 * 4 * 16];     // shortcut: C=32, NG=4

// ------------------------------ helpers -------------------------------------
__device__ __forceinline__ void split2(float x, __nv_bfloat16& h, __nv_bfloat16& l) {
    h = __float2bfloat16_rn(x);
    l = __float2bfloat16_rn(x - __bfloat162float(h));
}
__device__ __forceinline__ uint16_t bfbits(__nv_bfloat16 v) {
    return *(uint16_t*)&v;
}
// u16-index inside a 16-elem k-group for element j (0..15):
// order [0,1,8,9, 2,3,10,11, 4,5,12,13, 6,7,14,15]
__device__ __forceinline__ int pidx(int j) {
    return ((j & 6) << 1) | ((j & 8) >> 2) | (j & 1);
}
// interleaved group store: 64B = [hi(p) 8B | lo(p) 8B] x 4 quads
__device__ __forceinline__ void st64i(char* p, const __nv_bfloat16* hi,
                                      const __nv_bfloat16* lo) {
    __nv_bfloat16 comb[32];
    #pragma unroll
    for (int q = 0; q < 4; q++) {
        #pragma unroll
        for (int r = 0; r < 4; r++) {
            comb[q * 8 + r]     = hi[q * 4 + r];
            comb[q * 8 + 4 + r] = lo[q * 4 + r];
        }
    }
    #pragma unroll
    for (int q = 0; q < 4; q++)
        *(uint4*)(p + q * 16) = ((const uint4*)comb)[q];
}
__device__ __forceinline__ void mma16816(float& d0, float& d1, float& d2, float& d3,
                                         uint32_t a0, uint32_t a1, uint32_t a2, uint32_t a3,
                                         uint32_t b0, uint32_t b1) {
    asm volatile(
        "mma.sync.aligned.m16n8k16.row.col.f32.bf16.bf16.f32 "
        "{%0,%1,%2,%3}, {%4,%5,%6,%7}, {%8,%9}, {%0,%1,%2,%3};"
        : "+f"(d0), "+f"(d1), "+f"(d2), "+f"(d3)
        : "r"(a0), "r"(a1), "r"(a2), "r"(a3), "r"(b0), "r"(b1));
}

// --------------------- W fragment table build (device fn) -------------------
template<int C>
__device__ __forceinline__ void wext_body(const float* __restrict__ W,
                                          uint16_t* __restrict__ dst) {
    constexpr int SEG = (C + 15) & ~15;
    constexpr int S16 = SEG / 16;
    constexpr int NG  = 2 * S16;
    int tid = threadIdx.x;
    for (int i = tid; i < 64 * NG * 16; i += 256) dst[i] = 0;
    __syncthreads();
    for (int i = tid; i < 64 * C; i += 256) {
        int o = i / C, c = i % C;
        __nv_bfloat16 wh, wl; split2(W[i], wh, wl);
        int g = c >> 4, pj = pidx(c & 15);
        dst[(o * NG + g) * 16 + pj]       = bfbits(wh);
        dst[(o * NG + S16 + g) * 16 + pj] = bfbits(wl);
    }
}

// ------------------- prep: W tables (blocks 0-3) + init (4+) ----------------
__global__ void k_prep(const float* __restrict__ W0, const float* __restrict__ W1,
                       const float* __restrict__ W2, const float* __restrict__ Wsc) {
    int blk = blockIdx.x;
    if (blk == 0)      { wext_body<68>(W0,  g_wx0);  return; }
    else if (blk == 1) { wext_body<64>(W1,  g_wx1);  return; }
    else if (blk == 2) { wext_body<64>(W2,  g_wx2);  return; }
    else if (blk == 3) { wext_body<32>(Wsc, g_wxsc); return; }
    int i = (blk - 4) * blockDim.x + threadIdx.x;
    int stride = (gridDim.x - 4) * blockDim.x;
    for (int j = i; j < M_ALL; j += stride) g_topidx[j] = NN - 1;
    for (int j = i; j < BB * EIN * NN * KK; j += stride) g_eft[j] = 0.f;
    if (i < O0) {
        #pragma unroll
        for (int l = 0; l < 4; l++) { g_sum[l][i] = 0.f; g_sqsum[l][i] = 0.f; }
    }
}

// ----------------- features transpose: [B][C][N] -> [B][N][C] ---------------
__global__ void k_transpose(const float* __restrict__ F) {
    __shared__ float tile[32][33];
    int b = blockIdx.y, n0 = blockIdx.x * 32;
    int tx = threadIdx.x, ty = threadIdx.y;
    #pragma unroll
    for (int i = 0; i < 4; i++) {
        int c = ty + i * 8;
        tile[c][tx] = F[((size_t)b * CIN + c) * NN + n0 + tx];
    }
    __syncthreads();
    #pragma unroll
    for (int i = 0; i < 4; i++) {
        int n = ty + i * 8;
        g_featT[((size_t)b * NN + n0 + n) * CIN + tx] = tile[tx][n];
    }
}

// ------------------------------ edge scatter --------------------------------
__global__ void k_scatter(const int* __restrict__ edge_list,
                          const float* __restrict__ edge_feat) {
    int t = blockIdx.x * blockDim.x + threadIdx.x;
    if (t >= BB * PP) return;
    int b = t / PP, p = t % PP;
    const int* src = edge_list + (size_t)b * 2 * PP;
    const int* dst = src + PP;
    int s = src[p];
    int lo = 0, hi = p;
    while (lo < hi) { int mid = (lo + hi) >> 1; if (src[mid] < s) lo = mid + 1; else hi = mid; }
    int rank = p - lo;
    if (rank < KK) {
        g_topidx[(b * NN + s) * KK + rank] = dst[p];
        #pragma unroll
        for (int e = 0; e < EIN; e++)
            g_eft[((b * EIN + e) * NN + s) * KK + rank] =
                edge_feat[((size_t)b * EIN + e) * PP + p];
    }
}

// --------------- fused fallback-detect + knn (warp per node) ----------------
__global__ void k_knn2(const float* __restrict__ points) {
    int lane = threadIdx.x & 31;
    int warp = (blockIdx.x * blockDim.x + threadIdx.x) >> 5;
    int nwarps = (gridDim.x * blockDim.x) >> 5;
    for (int bn = warp; bn < BB * NN; bn += nwarps) {
        if (g_topidx[bn * KK] != NN - 1) continue;   // has edges -> skip
        int b = bn >> 10, n = bn & 1023;
        const float* px = points + (size_t)b * 2 * NN;
        const float* py = px + NN;
        float pxn = px[n], pyn = py[n];
        float xxn = pxn * pxn + pyn * pyn;
        float pd[32];
        #pragma unroll
        for (int r = 0; r < 32; r++) {
            int m = r * 32 + lane;
            float xm = px[m], ym = py[m];
            float inner = -2.0f * (pxn * xm + pyn * ym);
            float xxm = xm * xm + ym * ym;
            float v = -xxn - inner - xxm;
            pd[r] = (m == n) ? -INFINITY : v;
        }
        for (int kk = 0; kk < KK; kk++) {
            float bv = pd[0]; int br = 0;
            #pragma unroll
            for (int r = 1; r < 32; r++)
                if (pd[r] > bv) { bv = pd[r]; br = r; }
            int bi = br * 32 + lane;
            #pragma unroll
            for (int off = 16; off; off >>= 1) {
                float ov = __shfl_xor_sync(0xffffffffu, bv, off);
                int   oi = __shfl_xor_sync(0xffffffffu, bi, off);
                if (ov > bv || (ov == bv && oi < bi)) { bv = ov; bi = oi; }
            }
            if (lane == (bi & 31)) pd[bi >> 5] = -INFINITY;
            if (lane == 0) g_topidx[bn * KK + kk] = bi;
        }
    }
}

// --------------------------- mma GEMM + BN stats -----------------------------
// Sout[64][M] = W[64][C] * X[C][M].  X smem: S16 groups of 64B, interleaved
// [hi(p) 8B | lo(p) 8B]. Inner loop: 1 LDS.128 per group -> 3 mma per A-block.
// Warp split: C==68 -> 4cg x 2mh (16 out-ch, 64 cols); C<=64 -> 2cg x 4mh
// (32 out-ch via 2 A-blocks, 32 cols) so each B fragment feeds 6 mma.
template<int C, int MODE>
__device__ __forceinline__ void gemm_body(
    const uint16_t* __restrict__ Wx,
    const float* __restrict__ F,
    float* __restrict__ Sout,
    int statsIdx, int prevIdx, int Mtot, int bid, char* sm)
{
    constexpr int SEG  = (C + 15) & ~15;     // 80 / 64 / 32
    constexpr int S16  = SEG / 16;           // 5 / 4 / 2
    constexpr int NG   = 2 * S16;            // W-table groups
    constexpr int RB0  = S16 * 64;           // 320 / 256 / 128
    constexpr int ROWB = RB0 + (((RB0 % 128) == 64) ? 0 : 64);  // 320/320/192
    constexpr int XOFF = 1024;
    constexpr bool TWO_CG = (C != 68);

    float* sred = (float*)(sm + 512);    // [128] block stats (sum | sqsum)
    char*  Xs   = sm + XOFF;

    int tid = threadIdx.x;
    int wid = tid >> 5, lane = tid & 31;
    int gm0 = bid * 128;

    // ---- phase 1: consts ----
    if (tid < 128) sred[tid] = 0.f;
    if (MODE == 1 && tid < 128)
        ((float*)sm)[tid] = (tid < 64) ? g_a[prevIdx][tid] : g_c[prevIdx][tid - 64];
    __syncthreads();

    // ---- phase 2: X build (m = tid&127; h = channel half) ----
    {
        int m = tid & 127, h = tid >> 7;
        int gm = gm0 + m;
        char* rowp = Xs + m * ROWB;
        if (MODE == 0) {
            int b = gm >> 14, mloc = gm & 16383;
            int n = mloc >> 4;
            int ng = g_topidx[gm];
            const float* rowN = F + ((size_t)b * NN + n) * CIN;   // featT rows
            const float* rowG = F + ((size_t)b * NN + ng) * CIN;
            #pragma unroll
            for (int blk2 = 0; blk2 < 2; blk2++) {
                float xiv[16];
                #pragma unroll
                for (int q = 0; q < 4; q++)
                    *(float4*)(xiv + 4 * q) = *(const float4*)(rowN + blk2 * 16 + 4 * q);
                float xnv[16];
                if (h) {
                    #pragma unroll
                    for (int q = 0; q < 4; q++)
                        *(float4*)(xnv + 4 * q) = *(const float4*)(rowG + blk2 * 16 + 4 * q);
                }
                __nv_bfloat16 hi[16], lo[16];
                #pragma unroll
                for (int j = 0; j < 16; j++) {
                    float v = h ? (xnv[j] - xiv[j]) : xiv[j];
                    int pi = pidx(j);
                    split2(v, hi[pi], lo[pi]);
                }
                st64i(rowp + (h * 2 + blk2) * 64, hi, lo);
            }
            if (h == 1) {   // edge features k=64..67 -> group 4 (full, zero pad)
                __nv_bfloat16 eh[16], el[16];
                #pragma unroll
                for (int j = 0; j < 16; j++) { eh[j] = __nv_bfloat16(0.f); el[j] = __nv_bfloat16(0.f); }
                #pragma unroll
                for (int e = 0; e < 4; e++) {
                    float v = g_eft[(b * EIN + e) * (NN * KK) + mloc];
                    int pi = pidx(e);
                    split2(v, eh[pi], el[pi]);
                }
                st64i(rowp + 4 * 64, eh, el);
            }
        } else if (MODE == 1) {
            const float* ca2 = (const float*)sm;
            const float* cb2 = ca2 + 64;
            #pragma unroll
            for (int blk2 = 0; blk2 < 2; blk2++) {
                __nv_bfloat16 hi[16], lo[16];
                #pragma unroll
                for (int j = 0; j < 16; j++) {
                    int c = h * 32 + blk2 * 16 + j;
                    float v = F[(size_t)c * Mtot + gm];
                    float x = fmaxf(fmaf(ca2[c], v, cb2[c]), 0.f);
                    int pi = pidx(j);
                    split2(x, hi[pi], lo[pi]);
                }
                st64i(rowp + (h * 2 + blk2) * 64, hi, lo);
            }
        } else {            // MODE 2 (shortcut, C=32): one group per h
            int b = gm >> 10, n = gm & 1023;
            __nv_bfloat16 hi[16], lo[16];
            #pragma unroll
            for (int j = 0; j < 16; j++) {
                int c = h * 16 + j;
                float v = F[(size_t)(b * CIN + c) * NN + n];
                int pi = pidx(j);
                split2(v, hi[pi], lo[pi]);
            }
            st64i(rowp + h * 64, hi, lo);
        }
    }

    int g = lane >> 2, p = lane & 3;

    if constexpr (!TWO_CG) {
        // ---- 4cg x 2mh path (layer 0) ----
        int cg = wid & 3, mh = wid >> 2;
        int no = cg * 16;
        uint2 A02[NG], A13[NG];
        #pragma unroll
        for (int s = 0; s < NG; s++) {
            A02[s] = *(const uint2*)(Wx + (no + g) * (NG * 16) + s * 16 + p * 4);
            A13[s] = *(const uint2*)(Wx + (no + g + 8) * (NG * 16) + s * 16 + p * 4);
        }
        __syncthreads();

        float sA = 0.f, qA = 0.f, sB = 0.f, qB = 0.f;
        float* outA = Sout + (size_t)(no + g) * Mtot + gm0 + mh * 64 + 2 * p;
        float* outB = Sout + (size_t)(no + g + 8) * Mtot + gm0 + mh * 64 + 2 * p;
        #pragma unroll
        for (int ch = 0; ch < 8; ch++) {
            int m0 = mh * 64 + ch * 8;
            const char* brow = Xs + (m0 + g) * ROWB + p * 16;
            float d0 = 0.f, d1 = 0.f, d2 = 0.f, d3 = 0.f;
            #pragma unroll
            for (int s = 0; s < S16; s++) {
                uint4 bv = *(const uint4*)(brow + s * 64);
                mma16816(d0, d1, d2, d3, A02[s].x, A13[s].x, A02[s].y, A13[s].y, bv.x, bv.y);
                mma16816(d0, d1, d2, d3, A02[s].x, A13[s].x, A02[s].y, A13[s].y, bv.z, bv.w);
                mma16816(d0, d1, d2, d3, A02[S16 + s].x, A13[S16 + s].x,
                         A02[S16 + s].y, A13[S16 + s].y, bv.x, bv.y);
            }
            *(float2*)(outA + ch * 8) = make_float2(d0, d1);
            *(float2*)(outB + ch * 8) = make_float2(d2, d3);
            sA += d0 + d1;  qA += d0 * d0 + d1 * d1;
            sB += d2 + d3;  qB += d2 * d2 + d3 * d3;
        }
        #pragma unroll
        for (int off = 1; off <= 2; off <<= 1) {
            sA += __shfl_xor_sync(0xffffffffu, sA, off);
            qA += __shfl_xor_sync(0xffffffffu, qA, off);
            sB += __shfl_xor_sync(0xffffffffu, sB, off);
            qB += __shfl_xor_sync(0xffffffffu, qB, off);
        }
        if (p == 0) {
            atomicAdd(&sred[no + g], sA);
            atomicAdd(&sred[64 + no + g], qA);
            atomicAdd(&sred[no + g + 8], sB);
            atomicAdd(&sred[64 + no + g + 8], qB);
        }
    } else {
        // ---- 2cg x 4mh path (C<=64): B fragment feeds 6 mma ----
        int cg = wid & 1, mh = wid >> 1;
        int no = cg * 32;
        uint2 A02[2][NG], A13[2][NG];
        #pragma unroll
        for (int r2 = 0; r2 < 2; r2++)
            #pragma unroll
            for (int s = 0; s < NG; s++) {
                A02[r2][s] = *(const uint2*)(Wx + (no + r2 * 16 + g) * (NG * 16) + s * 16 + p * 4);
                A13[r2][s] = *(const uint2*)(Wx + (no + r2 * 16 + g + 8) * (NG * 16) + s * 16 + p * 4);
            }
        __syncthreads();

        float acc[2][4][4];
        #pragma unroll
        for (int r2 = 0; r2 < 2; r2++)
            #pragma unroll
            for (int ch = 0; ch < 4; ch++)
                #pragma unroll
                for (int j = 0; j < 4; j++) acc[r2][ch][j] = 0.f;

        #pragma unroll
        for (int ch = 0; ch < 4; ch++) {
            const char* brow = Xs + (mh * 32 + ch * 8 + g) * ROWB + p * 16;
            #pragma unroll
            for (int s = 0; s < S16; s++) {
                uint4 bv = *(const uint4*)(brow + s * 64);
                #pragma unroll
                for (int r2 = 0; r2 < 2; r2++) {
                    mma16816(acc[r2][ch][0], acc[r2][ch][1], acc[r2][ch][2], acc[r2][ch][3],
                             A02[r2][s].x, A13[r2][s].x, A02[r2][s].y, A13[r2][s].y, bv.x, bv.y);
                    mma16816(acc[r2][ch][0], acc[r2][ch][1], acc[r2][ch][2], acc[r2][ch][3],
                             A02[r2][s].x, A13[r2][s].x, A02[r2][s].y, A13[r2][s].y, bv.z, bv.w);
                    mma16816(acc[r2][ch][0], acc[r2][ch][1], acc[r2][ch][2], acc[r2][ch][3],
                             A02[r2][S16 + s].x, A13[r2][S16 + s].x,
                             A02[r2][S16 + s].y, A13[r2][S16 + s].y, bv.x, bv.y);
                }
            }
        }

        #pragma unroll
        for (int r2 = 0; r2 < 2; r2++) {
            int rowA = no + r2 * 16 + g;
            float* outA = Sout + (size_t)rowA * Mtot + gm0 + mh * 32 + 2 * p;
            float* outB = Sout + (size_t)(rowA + 8) * Mtot + gm0 + mh * 32 + 2 * p;
            float sA = 0.f, qA = 0.f, sB = 0.f, qB = 0.f;
            #pragma unroll
            for (int ch = 0; ch < 4; ch++) {
                float d0 = acc[r2][ch][0], d1 = acc[r2][ch][1];
                float d2 = acc[r2][ch][2], d3 = acc[r2][ch][3];
                *(float2*)(outA + ch * 8) = make_float2(d0, d1);
                *(float2*)(outB + ch * 8) = make_float2(d2, d3);
                sA += d0 + d1;  qA += d0 * d0 + d1 * d1;
                sB += d2 + d3;  qB += d2 * d2 + d3 * d3;
            }
            #pragma unroll
            for (int off = 1; off <= 2; off <<= 1) {
                sA += __shfl_xor_sync(0xffffffffu, sA, off);
                qA += __shfl_xor_sync(0xffffffffu, qA, off);
                sB += __shfl_xor_sync(0xffffffffu, sB, off);
                qB += __shfl_xor_sync(0xffffffffu, qB, off);
            }
            if (p == 0) {
                atomicAdd(&sred[rowA], sA);
                atomicAdd(&sred[64 + rowA], qA);
                atomicAdd(&sred[rowA + 8], sB);
                atomicAdd(&sred[64 + rowA + 8], qB);
            }
        }
    }

    __syncthreads();
    if (tid < 64)        atomicAdd(&g_sum[statsIdx][tid], sred[tid]);
    else if (tid < 128)  atomicAdd(&g_sqsum[statsIdx][tid - 64], sred[tid]);
}

// layer0 + shortcut in one launch: blocks 0-255 shortcut, 256+ layer 0
__global__ __launch_bounds__(256, 3) void k_gemm0sc(
    const uint16_t* __restrict__ Wx0, const uint16_t* __restrict__ WxSC,
    const float* __restrict__ F, const float* __restrict__ FT,
    float* __restrict__ S0, float* __restrict__ SC)
{
    extern __shared__ __align__(16) char sm[];
    if (blockIdx.x < M_SC / 128)
        gemm_body<32, 2>(WxSC, F, SC, 3, 0, M_SC, blockIdx.x, sm);
    else
        gemm_body<68, 0>(Wx0, FT, S0, 0, 0, M_ALL, blockIdx.x - M_SC / 128, sm);
}

template<int C, int MODE>
__global__ __launch_bounds__(256, 2) void k_gemm(
    const uint16_t* __restrict__ Wx,
    const float* __restrict__ F,
    float* __restrict__ Sout,
    int statsIdx, int prevIdx, int Mtot)
{
    extern __shared__ __align__(16) char sm[];
    gemm_body<C, MODE>(Wx, F, Sout, statsIdx, prevIdx, Mtot, blockIdx.x, sm);
}

// ------------------------------ finalize BN ---------------------------------
__global__ void k_finalize(const float* __restrict__ gamma,
                           const float* __restrict__ beta,
                           int idx, float invM) {
    int o = threadIdx.x;
    if (o < O0) {
        float m = g_sum[idx][o] * invM;
        float v = g_sqsum[idx][o] * invM - m * m;
        float a = gamma[o] / sqrtf(v + BN_EPS);
        g_a[idx][o] = a;
        g_c[idx][o] = beta[o] - m * a;
    }
}

// merged finalize for idx 2 (tid<64) and idx 3 (tid>=64)
__global__ void k_finalize23(const float* __restrict__ g2, const float* __restrict__ b2,
                             const float* __restrict__ g3, const float* __restrict__ b3) {
    int t = threadIdx.x;
    int idx = (t < 64) ? 2 : 3;
    int o = t & 63;
    float invM = (t < 64) ? (1.f / (float)M_ALL) : (1.f / (float)M_SC);
    const float* gg = (t < 64) ? g2 : g3;
    const float* bb = (t < 64) ? b2 : b3;
    float m = g_sum[idx][o] * invM;
    float v = g_sqsum[idx][o] * invM - m * m;
    float a = gg[o] / sqrtf(v + BN_EPS);
    g_a[idx][o] = a;
    g_c[idx][o] = bb[o] - m * a;
}

// ------------------------------ final fuse ----------------------------------
__global__ void k_final(float* __restrict__ out) {
    int t = blockIdx.x * blockDim.x + threadIdx.x;
    if (t >= BB * O0 * NN) return;
    int n = t & (NN - 1);
    int o = (t >> 10) & 63;
    int b = t >> 16;
    float a2 = g_a[2][o], c2 = g_c[2][o];
    const float4* S = (const float4*)(g_S0 + (size_t)o * M_ALL + b * (NN * KK) + n * KK);
    float s = 0.f;
    #pragma unroll
    for (int q = 0; q < 4; q++) {
        float4 v = S[q];
        s += fmaxf(fmaf(a2, v.x, c2), 0.f) + fmaxf(fmaf(a2, v.y, c2), 0.f)
           + fmaxf(fmaf(a2, v.z, c2), 0.f) + fmaxf(fmaf(a2, v.w, c2), 0.f);
    }
    float fts = s * (1.f / KK);
    float sc = g_scb[(size_t)o * M_SC + b * NN + n];
    float v = fmaf(g_a[3][o], sc, g_c[3][o]) + fts;
    out[t] = fmaxf(v, 0.f);
}

// ------------------------------- launch -------------------------------------
extern "C" void kernel_launch(void* const* d_in, const int* in_sizes, int n_in,
                              void* d_out, int out_size) {
    const float* points    = (const float*)d_in[0];
    const float* features  = (const float*)d_in[1];
    const int*   edge_list = (const int*)d_in[2];
    const float* edge_feat = (const float*)d_in[3];
    int base = (n_in >= 17 && in_sizes[4] == 1) ? 5 : 4;
    const float* W0   = (const float*)d_in[base + 0];
    const float* W1   = (const float*)d_in[base + 1];
    const float* W2   = (const float*)d_in[base + 2];
    const float* g0   = (const float*)d_in[base + 3];
    const float* b0   = (const float*)d_in[base + 4];
    const float* g1   = (const float*)d_in[base + 5];
    const float* b1   = (const float*)d_in[base + 6];
    const float* g2   = (const float*)d_in[base + 7];
    const float* b2   = (const float*)d_in[base + 8];
    const float* sc_w = (const float*)d_in[base + 9];
    const float* sc_g = (const float*)d_in[base + 10];
    const float* sc_b = (const float*)d_in[base + 11];

    void *pS0, *pS1, *pSC, *pW0, *pW1, *pW2, *pWS, *pFT;
    cudaGetSymbolAddress(&pS0, g_S0);
    cudaGetSymbolAddress(&pS1, g_S1);
    cudaGetSymbolAddress(&pSC, g_scb);
    cudaGetSymbolAddress(&pW0, g_wx0);
    cudaGetSymbolAddress(&pW1, g_wx1);
    cudaGetSymbolAddress(&pW2, g_wx2);
    cudaGetSymbolAddress(&pWS, g_wxsc);
    cudaGetSymbolAddress(&pFT, g_featT);
    float* S0 = (float*)pS0;
    float* S1 = (float*)pS1;
    float* SC = (float*)pSC;

    // smem: 1024 ctrl + Xs (ROWB: layer0 320, layer1/2 320, shortcut 192)
    const int smem0  = 1024 + 128 * 320;   // 41984 (covers shortcut too)
    const int smem1  = 1024 + 128 * 320;   // 41984
    cudaFuncSetAttribute(k_gemm0sc, cudaFuncAttributeMaxDynamicSharedMemorySize, smem0);
    cudaFuncSetAttribute(k_gemm<64, 1>, cudaFuncAttributeMaxDynamicSharedMemorySize, smem1);

    k_prep<<<516, 256>>>(W0, W1, W2, sc_w);
    k_transpose<<<dim3(NN / 32, BB), dim3(32, 8)>>>(features);
    k_scatter<<<(BB * PP + 255) / 256, 256>>>(edge_list, edge_feat);
    k_knn2<<<256, 256>>>(points);

    k_gemm0sc<<<M_SC / 128 + M_ALL / 128, 256, smem0>>>(
        (const uint16_t*)pW0, (const uint16_t*)pWS, features, (const float*)pFT, S0, SC);
    k_finalize<<<1, 64>>>(g0, b0, 0, 1.f / (float)M_ALL);
    k_gemm<64, 1><<<M_ALL / 128, 256, smem1>>>((const uint16_t*)pW1, S0, S1, 1, 0, M_ALL);
    k_finalize<<<1, 64>>>(g1, b1, 1, 1.f / (float)M_ALL);
    k_gemm<64, 1><<<M_ALL / 128, 256, smem1>>>((const uint16_t*)pW2, S1, S0, 2, 1, M_ALL);
    k_finalize23<<<1, 128>>>(g2, b2, sc_g, sc_b);

    k_final<<<(BB * O0 * NN + 255) / 256, 256>>>((float*)d_out);
}

// round 15
// speedup vs baseline: 1.1074x; 1.1074x over previous
#include <cuda_runtime.h>
#include <cuda_bf16.h>
#include <math.h>
#include <stdint.h>

// ---------------------------------------------------------------------------
// EdgeFeatureConvBlock  (B=32, N=1024, P=8192, K=16, C_IN=32, E_IN=4, OUT=64)
// R15: R13 GEMMs restored exactly (4cg x 2mh, occ 3 — R14's 2cg split lost
//      occupancy and regressed). Serial-chain cuts: (1) k_knn2 one-warp-per-
//      node single pass (scan was 16 dependent LDG chains -> 1 load),
//      (2) transpose merged into k_prep.
// ---------------------------------------------------------------------------

#define BB   32
#define NN   1024
#define PP   8192
#define KK   16
#define CIN  32
#define EIN  4
#define O0   64
#define M_ALL (BB*NN*KK) // 524288
#define M_SC  (BB*NN)    // 32768
#define BN_EPS 1e-5f

// ------------------------- scratch (device globals) ------------------------
__device__ float g_S0[(size_t)O0 * M_ALL];   // [64][M]
__device__ float g_S1[(size_t)O0 * M_ALL];
__device__ float g_scb[(size_t)O0 * M_SC];
__device__ float g_featT[BB * NN * CIN];     // node-major features
__device__ int   g_topidx[M_ALL];
__device__ float g_eft[BB * EIN * NN * KK];
__device__ float g_sum[4][O0];
__device__ float g_sqsum[4][O0];
__device__ float g_a[4][O0];
__device__ float g_c[4][O0];
// W fragment tables: [64][NG][16 u16] permuted (hi groups then lo groups)
__device__ uint16_t g_wx0[64 * 10 * 16];     // layer0: C=68, NG=10
__device__ uint16_t g_wx1[64 * 8 * 16];      // layer1: C=64, NG=8
__device__ uint16_t g_wx2[64 * 8 * 16];      // layer2: C=64, NG=8
__device__ uint16_t g_wxsc[64 * 4 * 16];     // shortcut: C=32, NG=4

// ------------------------------ helpers -------------------------------------
__device__ __forceinline__ void split2(float x, __nv_bfloat16& h, __nv_bfloat16& l) {
    h = __float2bfloat16_rn(x);
    l = __float2bfloat16_rn(x - __bfloat162float(h));
}
__device__ __forceinline__ uint16_t bfbits(__nv_bfloat16 v) {
    return *(uint16_t*)&v;
}
// u16-index inside a 16-elem k-group for element j (0..15):
// order [0,1,8,9, 2,3,10,11, 4,5,12,13, 6,7,14,15]
__device__ __forceinline__ int pidx(int j) {
    return ((j & 6) << 1) | ((j & 8) >> 2) | (j & 1);
}
// interleaved group store: 64B = [hi(p) 8B | lo(p) 8B] x 4 quads
__device__ __forceinline__ void st64i(char* p, const __nv_bfloat16* hi,
                                      const __nv_bfloat16* lo) {
    __nv_bfloat16 comb[32];
    #pragma unroll
    for (int q = 0; q < 4; q++) {
        #pragma unroll
        for (int r = 0; r < 4; r++) {
            comb[q * 8 + r]     = hi[q * 4 + r];
            comb[q * 8 + 4 + r] = lo[q * 4 + r];
        }
    }
    #pragma unroll
    for (int q = 0; q < 4; q++)
        *(uint4*)(p + q * 16) = ((const uint4*)comb)[q];
}
__device__ __forceinline__ void mma16816(float& d0, float& d1, float& d2, float& d3,
                                         uint32_t a0, uint32_t a1, uint32_t a2, uint32_t a3,
                                         uint32_t b0, uint32_t b1) {
    asm volatile(
        "mma.sync.aligned.m16n8k16.row.col.f32.bf16.bf16.f32 "
        "{%0,%1,%2,%3}, {%4,%5,%6,%7}, {%8,%9}, {%0,%1,%2,%3};"
        : "+f"(d0), "+f"(d1), "+f"(d2), "+f"(d3)
        : "r"(a0), "r"(a1), "r"(a2), "r"(a3), "r"(b0), "r"(b1));
}

// --------------------- W fragment table build (device fn) -------------------
template<int C>
__device__ __forceinline__ void wext_body(const float* __restrict__ W,
                                          uint16_t* __restrict__ dst) {
    constexpr int SEG = (C + 15) & ~15;
    constexpr int S16 = SEG / 16;
    constexpr int NG  = 2 * S16;
    int tid = threadIdx.x;
    for (int i = tid; i < 64 * NG * 16; i += 256) dst[i] = 0;
    __syncthreads();
    for (int i = tid; i < 64 * C; i += 256) {
        int o = i / C, c = i % C;
        __nv_bfloat16 wh, wl; split2(W[i], wh, wl);
        int g = c >> 4, pj = pidx(c & 15);
        dst[(o * NG + g) * 16 + pj]       = bfbits(wh);
        dst[(o * NG + S16 + g) * 16 + pj] = bfbits(wl);
    }
}

// ---- prep: W tables (blocks 0-3) + transpose (4..1027) + init (1028+) ------
__global__ void k_prep(const float* __restrict__ W0, const float* __restrict__ W1,
                       const float* __restrict__ W2, const float* __restrict__ Wsc,
                       const float* __restrict__ F) {
    int blk = blockIdx.x;
    int tid = threadIdx.x;
    if (blk == 0)      { wext_body<68>(W0,  g_wx0);  return; }
    else if (blk == 1) { wext_body<64>(W1,  g_wx1);  return; }
    else if (blk == 2) { wext_body<64>(W2,  g_wx2);  return; }
    else if (blk == 3) { wext_body<32>(Wsc, g_wxsc); return; }
    else if (blk < 4 + BB * (NN / 32)) {
        // transpose one 32x32 tile: [B][C][N] -> featT[B][N][C]
        __shared__ float tile[32][33];
        int tileIdx = blk - 4;
        int b = tileIdx >> 5, n0 = (tileIdx & 31) * 32;
        int tx = tid & 31, ty = tid >> 5;   // 8 rows per pass
        #pragma unroll
        for (int i = 0; i < 4; i++) {
            int c = ty + i * 8;
            tile[c][tx] = F[((size_t)b * CIN + c) * NN + n0 + tx];
        }
        __syncthreads();
        #pragma unroll
        for (int i = 0; i < 4; i++) {
            int n = ty + i * 8;
            g_featT[((size_t)b * NN + n0 + n) * CIN + tx] = tile[tx][n];
        }
        return;
    }
    int base = 4 + BB * (NN / 32);
    int i = (blk - base) * blockDim.x + tid;
    int stride = (gridDim.x - base) * blockDim.x;
    for (int j = i; j < M_ALL; j += stride) g_topidx[j] = NN - 1;
    for (int j = i; j < BB * EIN * NN * KK; j += stride) g_eft[j] = 0.f;
    if (i < O0) {
        #pragma unroll
        for (int l = 0; l < 4; l++) { g_sum[l][i] = 0.f; g_sqsum[l][i] = 0.f; }
    }
}

// ------------------------------ edge scatter --------------------------------
__global__ void k_scatter(const int* __restrict__ edge_list,
                          const float* __restrict__ edge_feat) {
    int t = blockIdx.x * blockDim.x + threadIdx.x;
    if (t >= BB * PP) return;
    int b = t / PP, p = t % PP;
    const int* src = edge_list + (size_t)b * 2 * PP;
    const int* dst = src + PP;
    int s = src[p];
    int lo = 0, hi = p;
    while (lo < hi) { int mid = (lo + hi) >> 1; if (src[mid] < s) lo = mid + 1; else hi = mid; }
    int rank = p - lo;
    if (rank < KK) {
        g_topidx[(b * NN + s) * KK + rank] = dst[p];
        #pragma unroll
        for (int e = 0; e < EIN; e++)
            g_eft[((b * EIN + e) * NN + s) * KK + rank] =
                edge_feat[((size_t)b * EIN + e) * PP + p];
    }
}

// --------------- fused fallback-detect + knn (1 warp = 1 node) --------------
// Matches reference pd = -xx_n - (-2*dot) - xx_m; self excluded; stable top-16
// (greater value wins; on tie smaller index wins).
__global__ void k_knn2(const float* __restrict__ points) {
    int lane = threadIdx.x & 31;
    int bn = (blockIdx.x * blockDim.x + threadIdx.x) >> 5;
    if (bn >= BB * NN) return;
    if (g_topidx[bn * KK] != NN - 1) return;   // has edges -> skip
    int b = bn >> 10, n = bn & 1023;
    const float* px = points + (size_t)b * 2 * NN;
    const float* py = px + NN;
    float pxn = px[n], pyn = py[n];
    float xxn = pxn * pxn + pyn * pyn;
    float pd[32];
    #pragma unroll
    for (int r = 0; r < 32; r++) {
        int m = r * 32 + lane;
        float xm = px[m], ym = py[m];
        float inner = -2.0f * (pxn * xm + pyn * ym);
        float xxm = xm * xm + ym * ym;
        float v = -xxn - inner - xxm;
        pd[r] = (m == n) ? -INFINITY : v;
    }
    for (int kk = 0; kk < KK; kk++) {
        float bv = pd[0]; int br = 0;
        #pragma unroll
        for (int r = 1; r < 32; r++)
            if (pd[r] > bv) { bv = pd[r]; br = r; }
        int bi = br * 32 + lane;
        #pragma unroll
        for (int off = 16; off; off >>= 1) {
            float ov = __shfl_xor_sync(0xffffffffu, bv, off);
            int   oi = __shfl_xor_sync(0xffffffffu, bi, off);
            if (ov > bv || (ov == bv && oi < bi)) { bv = ov; bi = oi; }
        }
        if (lane == (bi & 31)) pd[bi >> 5] = -INFINITY;
        if (lane == 0) g_topidx[bn * KK + kk] = bi;
    }
}

// --------------------------- mma GEMM + BN stats -----------------------------
// Sout[64][M] = W[64][C] * X[C][M].  X smem: S16 groups of 64B, interleaved
// [hi(p) 8B | lo(p) 8B]. Inner loop: 1 LDS.128 per group -> 3 mma.
// CTA: 128 columns, 256 threads = 8 warps (4 channel-groups x 2 m-halves).
// MODE: 0 = gather-build 68ch (F = featT), 1 = relu(bn(Sin)), 2 = features.
template<int C, int MODE>
__device__ __forceinline__ void gemm_body(
    const uint16_t* __restrict__ Wx,
    const float* __restrict__ F,
    float* __restrict__ Sout,
    int statsIdx, int prevIdx, int Mtot, int bid, char* sm)
{
    constexpr int SEG  = (C + 15) & ~15;     // 80 / 64 / 32
    constexpr int S16  = SEG / 16;           // 5 / 4 / 2
    constexpr int NG   = 2 * S16;            // W-table groups
    constexpr int RB0  = S16 * 64;           // 320 / 256 / 128
    constexpr int ROWB = RB0 + (((RB0 % 128) == 64) ? 0 : 64);  // 320/320/192
    constexpr int XOFF = 1024;

    float* sred = (float*)(sm + 512);    // [128] block stats (sum | sqsum)
    char*  Xs   = sm + XOFF;

    int tid = threadIdx.x;
    int wid = tid >> 5, lane = tid & 31;
    int gm0 = bid * 128;

    // ---- phase 1: consts ----
    if (tid < 128) sred[tid] = 0.f;
    if (MODE == 1 && tid < 128)
        ((float*)sm)[tid] = (tid < 64) ? g_a[prevIdx][tid] : g_c[prevIdx][tid - 64];
    __syncthreads();

    // ---- phase 2: X build (m = tid&127; h = channel half) ----
    {
        int m = tid & 127, h = tid >> 7;
        int gm = gm0 + m;
        char* rowp = Xs + m * ROWB;
        if (MODE == 0) {
            int b = gm >> 14, mloc = gm & 16383;
            int n = mloc >> 4;
            int ng = g_topidx[gm];
            const float* rowN = F + ((size_t)b * NN + n) * CIN;   // featT rows
            const float* rowG = F + ((size_t)b * NN + ng) * CIN;
            #pragma unroll
            for (int blk2 = 0; blk2 < 2; blk2++) {
                float xiv[16];
                #pragma unroll
                for (int q = 0; q < 4; q++)
                    *(float4*)(xiv + 4 * q) = *(const float4*)(rowN + blk2 * 16 + 4 * q);
                float xnv[16];
                if (h) {
                    #pragma unroll
                    for (int q = 0; q < 4; q++)
                        *(float4*)(xnv + 4 * q) = *(const float4*)(rowG + blk2 * 16 + 4 * q);
                }
                __nv_bfloat16 hi[16], lo[16];
                #pragma unroll
                for (int j = 0; j < 16; j++) {
                    float v = h ? (xnv[j] - xiv[j]) : xiv[j];
                    int pi = pidx(j);
                    split2(v, hi[pi], lo[pi]);
                }
                st64i(rowp + (h * 2 + blk2) * 64, hi, lo);
            }
            if (h == 1) {   // edge features k=64..67 -> group 4 (full, zero pad)
                __nv_bfloat16 eh[16], el[16];
                #pragma unroll
                for (int j = 0; j < 16; j++) { eh[j] = __nv_bfloat16(0.f); el[j] = __nv_bfloat16(0.f); }
                #pragma unroll
                for (int e = 0; e < 4; e++) {
                    float v = g_eft[(b * EIN + e) * (NN * KK) + mloc];
                    int pi = pidx(e);
                    split2(v, eh[pi], el[pi]);
                }
                st64i(rowp + 4 * 64, eh, el);
            }
        } else if (MODE == 1) {
            const float* ca2 = (const float*)sm;
            const float* cb2 = ca2 + 64;
            #pragma unroll
            for (int blk2 = 0; blk2 < 2; blk2++) {
                __nv_bfloat16 hi[16], lo[16];
                #pragma unroll
                for (int j = 0; j < 16; j++) {
                    int c = h * 32 + blk2 * 16 + j;
                    float v = F[(size_t)c * Mtot + gm];
                    float x = fmaxf(fmaf(ca2[c], v, cb2[c]), 0.f);
                    int pi = pidx(j);
                    split2(x, hi[pi], lo[pi]);
                }
                st64i(rowp + (h * 2 + blk2) * 64, hi, lo);
            }
        } else {            // MODE 2 (shortcut, C=32): one group per h
            int b = gm >> 10, n = gm & 1023;
            __nv_bfloat16 hi[16], lo[16];
            #pragma unroll
            for (int j = 0; j < 16; j++) {
                int c = h * 16 + j;
                float v = F[(size_t)(b * CIN + c) * NN + n];
                int pi = pidx(j);
                split2(v, hi[pi], lo[pi]);
            }
            st64i(rowp + h * 64, hi, lo);
        }
    }

    // ---- phase 3: hoist W fragments from global table (cached) ----
    int cg = wid & 3, mh = wid >> 2;
    int no = cg * 16;
    int g = lane >> 2, p = lane & 3;
    uint2 A02[NG], A13[NG];
    #pragma unroll
    for (int s = 0; s < NG; s++) {
        A02[s] = *(const uint2*)(Wx + (no + g) * (NG * 16) + s * 16 + p * 4);
        A13[s] = *(const uint2*)(Wx + (no + g + 8) * (NG * 16) + s * 16 + p * 4);
    }
    __syncthreads();

    // ---- phase 4: mma main loop (1 LDS.128 per group -> 3 mma) ----
    float sA = 0.f, qA = 0.f, sB = 0.f, qB = 0.f;
    float* outA = Sout + (size_t)(no + g) * Mtot + gm0 + mh * 64 + 2 * p;
    float* outB = Sout + (size_t)(no + g + 8) * Mtot + gm0 + mh * 64 + 2 * p;
    #pragma unroll
    for (int ch = 0; ch < 8; ch++) {
        int m0 = mh * 64 + ch * 8;
        const char* brow = Xs + (m0 + g) * ROWB + p * 16;
        float d0 = 0.f, d1 = 0.f, d2 = 0.f, d3 = 0.f;
        #pragma unroll
        for (int s = 0; s < S16; s++) {
            uint4 bv = *(const uint4*)(brow + s * 64);
            mma16816(d0, d1, d2, d3, A02[s].x, A13[s].x, A02[s].y, A13[s].y, bv.x, bv.y);
            mma16816(d0, d1, d2, d3, A02[s].x, A13[s].x, A02[s].y, A13[s].y, bv.z, bv.w);
            mma16816(d0, d1, d2, d3, A02[S16 + s].x, A13[S16 + s].x,
                     A02[S16 + s].y, A13[S16 + s].y, bv.x, bv.y);
        }
        *(float2*)(outA + ch * 8) = make_float2(d0, d1);
        *(float2*)(outB + ch * 8) = make_float2(d2, d3);
        sA += d0 + d1;  qA += d0 * d0 + d1 * d1;
        sB += d2 + d3;  qB += d2 * d2 + d3 * d3;
    }

    // ---- phase 5: stats reduction (quad -> smem -> global) ----
    #pragma unroll
    for (int off = 1; off <= 2; off <<= 1) {
        sA += __shfl_xor_sync(0xffffffffu, sA, off);
        qA += __shfl_xor_sync(0xffffffffu, qA, off);
        sB += __shfl_xor_sync(0xffffffffu, sB, off);
        qB += __shfl_xor_sync(0xffffffffu, qB, off);
    }
    if (p == 0) {
        atomicAdd(&sred[no + g], sA);
        atomicAdd(&sred[64 + no + g], qA);
        atomicAdd(&sred[no + g + 8], sB);
        atomicAdd(&sred[64 + no + g + 8], qB);
    }
    __syncthreads();
    if (tid < 64)        atomicAdd(&g_sum[statsIdx][tid], sred[tid]);
    else if (tid < 128)  atomicAdd(&g_sqsum[statsIdx][tid - 64], sred[tid]);
}

// layer0 + shortcut in one launch: blocks 0-255 shortcut, 256+ layer 0
__global__ __launch_bounds__(256, 3) void k_gemm0sc(
    const uint16_t* __restrict__ Wx0, const uint16_t* __restrict__ WxSC,
    const float* __restrict__ F, const float* __restrict__ FT,
    float* __restrict__ S0, float* __restrict__ SC)
{
    extern __shared__ __align__(16) char sm[];
    if (blockIdx.x < M_SC / 128)
        gemm_body<32, 2>(WxSC, F, SC, 3, 0, M_SC, blockIdx.x, sm);
    else
        gemm_body<68, 0>(Wx0, FT, S0, 0, 0, M_ALL, blockIdx.x - M_SC / 128, sm);
}

template<int C, int MODE>
__global__ __launch_bounds__(256, 3) void k_gemm(
    const uint16_t* __restrict__ Wx,
    const float* __restrict__ F,
    float* __restrict__ Sout,
    int statsIdx, int prevIdx, int Mtot)
{
    extern __shared__ __align__(16) char sm[];
    gemm_body<C, MODE>(Wx, F, Sout, statsIdx, prevIdx, Mtot, blockIdx.x, sm);
}

// ------------------------------ finalize BN ---------------------------------
__global__ void k_finalize(const float* __restrict__ gamma,
                           const float* __restrict__ beta,
                           int idx, float invM) {
    int o = threadIdx.x;
    if (o < O0) {
        float m = g_sum[idx][o] * invM;
        float v = g_sqsum[idx][o] * invM - m * m;
        float a = gamma[o] / sqrtf(v + BN_EPS);
        g_a[idx][o] = a;
        g_c[idx][o] = beta[o] - m * a;
    }
}

// merged finalize for idx 2 (tid<64) and idx 3 (tid>=64)
__global__ void k_finalize23(const float* __restrict__ g2, const float* __restrict__ b2,
                             const float* __restrict__ g3, const float* __restrict__ b3) {
    int t = threadIdx.x;
    int idx = (t < 64) ? 2 : 3;
    int o = t & 63;
    float invM = (t < 64) ? (1.f / (float)M_ALL) : (1.f / (float)M_SC);
    const float* gg = (t < 64) ? g2 : g3;
    const float* bb = (t < 64) ? b2 : b3;
    float m = g_sum[idx][o] * invM;
    float v = g_sqsum[idx][o] * invM - m * m;
    float a = gg[o] / sqrtf(v + BN_EPS);
    g_a[idx][o] = a;
    g_c[idx][o] = bb[o] - m * a;
}

// ------------------------------ final fuse ----------------------------------
__global__ void k_final(float* __restrict__ out) {
    int t = blockIdx.x * blockDim.x + threadIdx.x;
    if (t >= BB * O0 * NN) return;
    int n = t & (NN - 1);
    int o = (t >> 10) & 63;
    int b = t >> 16;
    float a2 = g_a[2][o], c2 = g_c[2][o];
    const float4* S = (const float4*)(g_S0 + (size_t)o * M_ALL + b * (NN * KK) + n * KK);
    float s = 0.f;
    #pragma unroll
    for (int q = 0; q < 4; q++) {
        float4 v = S[q];
        s += fmaxf(fmaf(a2, v.x, c2), 0.f) + fmaxf(fmaf(a2, v.y, c2), 0.f)
           + fmaxf(fmaf(a2, v.z, c2), 0.f) + fmaxf(fmaf(a2, v.w, c2), 0.f);
    }
    float fts = s * (1.f / KK);
    float sc = g_scb[(size_t)o * M_SC + b * NN + n];
    float v = fmaf(g_a[3][o], sc, g_c[3][o]) + fts;
    out[t] = fmaxf(v, 0.f);
}

// ------------------------------- launch -------------------------------------
extern "C" void kernel_launch(void* const* d_in, const int* in_sizes, int n_in,
                              void* d_out, int out_size) {
    const float* points    = (const float*)d_in[0];
    const float* features  = (const float*)d_in[1];
    const int*   edge_list = (const int*)d_in[2];
    const float* edge_feat = (const float*)d_in[3];
    int base = (n_in >= 17 && in_sizes[4] == 1) ? 5 : 4;
    const float* W0   = (const float*)d_in[base + 0];
    const float* W1   = (const float*)d_in[base + 1];
    const float* W2   = (const float*)d_in[base + 2];
    const float* g0   = (const float*)d_in[base + 3];
    const float* b0   = (const float*)d_in[base + 4];
    const float* g1   = (const float*)d_in[base + 5];
    const float* b1   = (const float*)d_in[base + 6];
    const float* g2   = (const float*)d_in[base + 7];
    const float* b2   = (const float*)d_in[base + 8];
    const float* sc_w = (const float*)d_in[base + 9];
    const float* sc_g = (const float*)d_in[base + 10];
    const float* sc_b = (const float*)d_in[base + 11];

    void *pS0, *pS1, *pSC, *pW0, *pW1, *pW2, *pWS, *pFT;
    cudaGetSymbolAddress(&pS0, g_S0);
    cudaGetSymbolAddress(&pS1, g_S1);
    cudaGetSymbolAddress(&pSC, g_scb);
    cudaGetSymbolAddress(&pW0, g_wx0);
    cudaGetSymbolAddress(&pW1, g_wx1);
    cudaGetSymbolAddress(&pW2, g_wx2);
    cudaGetSymbolAddress(&pWS, g_wxsc);
    cudaGetSymbolAddress(&pFT, g_featT);
    float* S0 = (float*)pS0;
    float* S1 = (float*)pS1;
    float* SC = (float*)pSC;

    // smem: 1024 ctrl + Xs (ROWB: layer0 320, layer1/2 320, shortcut 192)
    const int smem0  = 1024 + 128 * 320;   // 41984 (covers shortcut too)
    const int smem1  = 1024 + 128 * 320;   // 41984
    cudaFuncSetAttribute(k_gemm0sc, cudaFuncAttributeMaxDynamicSharedMemorySize, smem0);
    cudaFuncSetAttribute(k_gemm<64, 1>, cudaFuncAttributeMaxDynamicSharedMemorySize, smem1);

    // prep grid: 4 wext + 1024 transpose tiles + 512 init blocks
    k_prep<<<4 + BB * (NN / 32) + 512, 256>>>(W0, W1, W2, sc_w, features);
    k_scatter<<<(BB * PP + 255) / 256, 256>>>(edge_list, edge_feat);
    k_knn2<<<BB * NN / 8, 256>>>(points);

    k_gemm0sc<<<M_SC / 128 + M_ALL / 128, 256, smem0>>>(
        (const uint16_t*)pW0, (const uint16_t*)pWS, features, (const float*)pFT, S0, SC);
    k_finalize<<<1, 64>>>(g0, b0, 0, 1.f / (float)M_ALL);
    k_gemm<64, 1><<<M_ALL / 128, 256, smem1>>>((const uint16_t*)pW1, S0, S1, 1, 0, M_ALL);
    k_finalize<<<1, 64>>>(g1, b1, 1, 1.f / (float)M_ALL);
    k_gemm<64, 1><<<M_ALL / 128, 256, smem1>>>((const uint16_t*)pW2, S1, S0, 2, 1, M_ALL);
    k_finalize23<<<1, 128>>>(g2, b2, sc_g, sc_b);

    k_final<<<(BB * O0 * NN + 255) / 256, 256>>>((float*)d_out);
}

// round 17
// speedup vs baseline: 1.1562x; 1.0440x over previous
#include <cuda_runtime.h>
#include <cuda_bf16.h>
#include <cuda_fp16.h>
#include <math.h>
#include <stdint.h>

// ---------------------------------------------------------------------------
// EdgeFeatureConvBlock  (B=32, N=1024, P=8192, K=16, C_IN=32, E_IN=4, OUT=64)
// R17: R15 base + inter-layer S buffers stored as fp16 (__half). bf16 (R16)
//      failed at rel_err 1.33e-3; fp16 has 3 more mantissa bits -> predicted
//      ~1.7e-4. Same byte savings: epilogue stores, MODE-1 loads, k_final
//      reads all halved vs fp32. BN stats stay fp32-exact. Shortcut fp32.
// ---------------------------------------------------------------------------

#define BB   32
#define NN   1024
#define PP   8192
#define KK   16
#define CIN  32
#define EIN  4
#define O0   64
#define M_ALL (BB*NN*KK) // 524288
#define M_SC  (BB*NN)    // 32768
#define BN_EPS 1e-5f

// ------------------------- scratch (device globals) ------------------------
__device__ __half g_S0[(size_t)O0 * M_ALL];  // [64][M] fp16
__device__ __half g_S1[(size_t)O0 * M_ALL];  // [64][M] fp16
__device__ float g_scb[(size_t)O0 * M_SC];   // fp32 (shortcut)
__device__ float g_featT[BB * NN * CIN];     // node-major features
__device__ int   g_topidx[M_ALL];
__device__ float g_eft[BB * EIN * NN * KK];
__device__ float g_sum[4][O0];
__device__ float g_sqsum[4][O0];
__device__ float g_a[4][O0];
__device__ float g_c[4][O0];
// W fragment tables: [64][NG][16 u16] permuted (hi groups then lo groups)
__device__ uint16_t g_wx0[64 * 10 * 16];     // layer0: C=68, NG=10
__device__ uint16_t g_wx1[64 * 8 * 16];      // layer1: C=64, NG=8
__device__ uint16_t g_wx2[64 * 8 * 16];      // layer2: C=64, NG=8
__device__ uint16_t g_wxsc[64 * 4 * 16];     // shortcut: C=32, NG=4

// ------------------------------ helpers -------------------------------------
__device__ __forceinline__ void split2(float x, __nv_bfloat16& h, __nv_bfloat16& l) {
    h = __float2bfloat16_rn(x);
    l = __float2bfloat16_rn(x - __bfloat162float(h));
}
__device__ __forceinline__ uint16_t bfbits(__nv_bfloat16 v) {
    return *(uint16_t*)&v;
}
// u16-index inside a 16-elem k-group for element j (0..15):
// order [0,1,8,9, 2,3,10,11, 4,5,12,13, 6,7,14,15]
__device__ __forceinline__ int pidx(int j) {
    return ((j & 6) << 1) | ((j & 8) >> 2) | (j & 1);
}
// interleaved group store: 64B = [hi(p) 8B | lo(p) 8B] x 4 quads
__device__ __forceinline__ void st64i(char* p, const __nv_bfloat16* hi,
                                      const __nv_bfloat16* lo) {
    __nv_bfloat16 comb[32];
    #pragma unroll
    for (int q = 0; q < 4; q++) {
        #pragma unroll
        for (int r = 0; r < 4; r++) {
            comb[q * 8 + r]     = hi[q * 4 + r];
            comb[q * 8 + 4 + r] = lo[q * 4 + r];
        }
    }
    #pragma unroll
    for (int q = 0; q < 4; q++)
        *(uint4*)(p + q * 16) = ((const uint4*)comb)[q];
}
__device__ __forceinline__ void mma16816(float& d0, float& d1, float& d2, float& d3,
                                         uint32_t a0, uint32_t a1, uint32_t a2, uint32_t a3,
                                         uint32_t b0, uint32_t b1) {
    asm volatile(
        "mma.sync.aligned.m16n8k16.row.col.f32.bf16.bf16.f32 "
        "{%0,%1,%2,%3}, {%4,%5,%6,%7}, {%8,%9}, {%0,%1,%2,%3};"
        : "+f"(d0), "+f"(d1), "+f"(d2), "+f"(d3)
        : "r"(a0), "r"(a1), "r"(a2), "r"(a3), "r"(b0), "r"(b1));
}

// --------------------- W fragment table build (device fn) -------------------
template<int C>
__device__ __forceinline__ void wext_body(const float* __restrict__ W,
                                          uint16_t* __restrict__ dst) {
    constexpr int SEG = (C + 15) & ~15;
    constexpr int S16 = SEG / 16;
    constexpr int NG  = 2 * S16;
    int tid = threadIdx.x;
    for (int i = tid; i < 64 * NG * 16; i += 256) dst[i] = 0;
    __syncthreads();
    for (int i = tid; i < 64 * C; i += 256) {
        int o = i / C, c = i % C;
        __nv_bfloat16 wh, wl; split2(W[i], wh, wl);
        int g = c >> 4, pj = pidx(c & 15);
        dst[(o * NG + g) * 16 + pj]       = bfbits(wh);
        dst[(o * NG + S16 + g) * 16 + pj] = bfbits(wl);
    }
}

// ---- prep: W tables (blocks 0-3) + transpose (4..1027) + init (1028+) ------
__global__ void k_prep(const float* __restrict__ W0, const float* __restrict__ W1,
                       const float* __restrict__ W2, const float* __restrict__ Wsc,
                       const float* __restrict__ F) {
    int blk = blockIdx.x;
    int tid = threadIdx.x;
    if (blk == 0)      { wext_body<68>(W0,  g_wx0);  return; }
    else if (blk == 1) { wext_body<64>(W1,  g_wx1);  return; }
    else if (blk == 2) { wext_body<64>(W2,  g_wx2);  return; }
    else if (blk == 3) { wext_body<32>(Wsc, g_wxsc); return; }
    else if (blk < 4 + BB * (NN / 32)) {
        __shared__ float tile[32][33];
        int tileIdx = blk - 4;
        int b = tileIdx >> 5, n0 = (tileIdx & 31) * 32;
        int tx = tid & 31, ty = tid >> 5;
        #pragma unroll
        for (int i = 0; i < 4; i++) {
            int c = ty + i * 8;
            tile[c][tx] = F[((size_t)b * CIN + c) * NN + n0 + tx];
        }
        __syncthreads();
        #pragma unroll
        for (int i = 0; i < 4; i++) {
            int n = ty + i * 8;
            g_featT[((size_t)b * NN + n0 + n) * CIN + tx] = tile[tx][n];
        }
        return;
    }
    int base = 4 + BB * (NN / 32);
    int i = (blk - base) * blockDim.x + tid;
    int stride = (gridDim.x - base) * blockDim.x;
    for (int j = i; j < M_ALL; j += stride) g_topidx[j] = NN - 1;
    for (int j = i; j < BB * EIN * NN * KK; j += stride) g_eft[j] = 0.f;
    if (i < O0) {
        #pragma unroll
        for (int l = 0; l < 4; l++) { g_sum[l][i] = 0.f; g_sqsum[l][i] = 0.f; }
    }
}

// ------------------------------ edge scatter --------------------------------
__global__ void k_scatter(const int* __restrict__ edge_list,
                          const float* __restrict__ edge_feat) {
    int t = blockIdx.x * blockDim.x + threadIdx.x;
    if (t >= BB * PP) return;
    int b = t / PP, p = t % PP;
    const int* src = edge_list + (size_t)b * 2 * PP;
    const int* dst = src + PP;
    int s = src[p];
    int lo = 0, hi = p;
    while (lo < hi) { int mid = (lo + hi) >> 1; if (src[mid] < s) lo = mid + 1; else hi = mid; }
    int rank = p - lo;
    if (rank < KK) {
        g_topidx[(b * NN + s) * KK + rank] = dst[p];
        #pragma unroll
        for (int e = 0; e < EIN; e++)
            g_eft[((b * EIN + e) * NN + s) * KK + rank] =
                edge_feat[((size_t)b * EIN + e) * PP + p];
    }
}

// --------------- fused fallback-detect + knn (1 warp = 1 node) --------------
__global__ void k_knn2(const float* __restrict__ points) {
    int lane = threadIdx.x & 31;
    int bn = (blockIdx.x * blockDim.x + threadIdx.x) >> 5;
    if (bn >= BB * NN) return;
    if (g_topidx[bn * KK] != NN - 1) return;   // has edges -> skip
    int b = bn >> 10, n = bn & 1023;
    const float* px = points + (size_t)b * 2 * NN;
    const float* py = px + NN;
    float pxn = px[n], pyn = py[n];
    float xxn = pxn * pxn + pyn * pyn;
    float pd[32];
    #pragma unroll
    for (int r = 0; r < 32; r++) {
        int m = r * 32 + lane;
        float xm = px[m], ym = py[m];
        float inner = -2.0f * (pxn * xm + pyn * ym);
        float xxm = xm * xm + ym * ym;
        float v = -xxn - inner - xxm;
        pd[r] = (m == n) ? -INFINITY : v;
    }
    for (int kk = 0; kk < KK; kk++) {
        float bv = pd[0]; int br = 0;
        #pragma unroll
        for (int r = 1; r < 32; r++)
            if (pd[r] > bv) { bv = pd[r]; br = r; }
        int bi = br * 32 + lane;
        #pragma unroll
        for (int off = 16; off; off >>= 1) {
            float ov = __shfl_xor_sync(0xffffffffu, bv, off);
            int   oi = __shfl_xor_sync(0xffffffffu, bi, off);
            if (ov > bv || (ov == bv && oi < bi)) { bv = ov; bi = oi; }
        }
        if (lane == (bi & 31)) pd[bi >> 5] = -INFINITY;
        if (lane == 0) g_topidx[bn * KK + kk] = bi;
    }
}

// --------------------------- mma GEMM + BN stats -----------------------------
// Sout[64][M] = W[64][C] * X[C][M].  X smem: S16 groups of 64B, interleaved
// [hi(p) 8B | lo(p) 8B]. Inner loop: 1 LDS.128 per group -> 3 mma.
// CTA: 128 columns, 256 threads = 8 warps (4 channel-groups x 2 m-halves).
// MODE: 0 = gather-build 68ch (featT fp32 -> S fp16), 1 = relu(bn(Sin fp16))
// -> S fp16, 2 = features fp32 -> SC fp32 (shortcut).
template<int C, int MODE>
__device__ __forceinline__ void gemm_body(
    const uint16_t* __restrict__ Wx,
    const void* __restrict__ Fv,
    void* __restrict__ Soutv,
    int statsIdx, int prevIdx, int Mtot, int bid, char* sm)
{
    constexpr int SEG  = (C + 15) & ~15;     // 80 / 64 / 32
    constexpr int S16  = SEG / 16;           // 5 / 4 / 2
    constexpr int NG   = 2 * S16;            // W-table groups
    constexpr int RB0  = S16 * 64;           // 320 / 256 / 128
    constexpr int ROWB = RB0 + (((RB0 % 128) == 64) ? 0 : 64);  // 320/320/192
    constexpr int XOFF = 1024;

    float* sred = (float*)(sm + 512);    // [128] block stats (sum | sqsum)
    char*  Xs   = sm + XOFF;

    int tid = threadIdx.x;
    int wid = tid >> 5, lane = tid & 31;
    int gm0 = bid * 128;

    // ---- phase 1: consts ----
    if (tid < 128) sred[tid] = 0.f;
    if (MODE == 1 && tid < 128)
        ((float*)sm)[tid] = (tid < 64) ? g_a[prevIdx][tid] : g_c[prevIdx][tid - 64];
    __syncthreads();

    // ---- phase 2: X build (m = tid&127; h = channel half) ----
    {
        int m = tid & 127, h = tid >> 7;
        int gm = gm0 + m;
        char* rowp = Xs + m * ROWB;
        if (MODE == 0) {
            const float* F = (const float*)Fv;
            int b = gm >> 14, mloc = gm & 16383;
            int n = mloc >> 4;
            int ng = g_topidx[gm];
            const float* rowN = F + ((size_t)b * NN + n) * CIN;
            const float* rowG = F + ((size_t)b * NN + ng) * CIN;
            #pragma unroll
            for (int blk2 = 0; blk2 < 2; blk2++) {
                float xiv[16];
                #pragma unroll
                for (int q = 0; q < 4; q++)
                    *(float4*)(xiv + 4 * q) = *(const float4*)(rowN + blk2 * 16 + 4 * q);
                float xnv[16];
                if (h) {
                    #pragma unroll
                    for (int q = 0; q < 4; q++)
                        *(float4*)(xnv + 4 * q) = *(const float4*)(rowG + blk2 * 16 + 4 * q);
                }
                __nv_bfloat16 hi[16], lo[16];
                #pragma unroll
                for (int j = 0; j < 16; j++) {
                    float v = h ? (xnv[j] - xiv[j]) : xiv[j];
                    int pi = pidx(j);
                    split2(v, hi[pi], lo[pi]);
                }
                st64i(rowp + (h * 2 + blk2) * 64, hi, lo);
            }
            if (h == 1) {
                __nv_bfloat16 eh[16], el[16];
                #pragma unroll
                for (int j = 0; j < 16; j++) { eh[j] = __nv_bfloat16(0.f); el[j] = __nv_bfloat16(0.f); }
                #pragma unroll
                for (int e = 0; e < 4; e++) {
                    float v = g_eft[(b * EIN + e) * (NN * KK) + mloc];
                    int pi = pidx(e);
                    split2(v, eh[pi], el[pi]);
                }
                st64i(rowp + 4 * 64, eh, el);
            }
        } else if (MODE == 1) {
            const __half* F = (const __half*)Fv;
            const float* ca2 = (const float*)sm;
            const float* cb2 = ca2 + 64;
            #pragma unroll
            for (int blk2 = 0; blk2 < 2; blk2++) {
                __nv_bfloat16 hi[16], lo[16];
                #pragma unroll
                for (int j = 0; j < 16; j++) {
                    int c = h * 32 + blk2 * 16 + j;
                    float v = __half2float(F[(size_t)c * Mtot + gm]);
                    float x = fmaxf(fmaf(ca2[c], v, cb2[c]), 0.f);
                    int pi = pidx(j);
                    split2(x, hi[pi], lo[pi]);
                }
                st64i(rowp + (h * 2 + blk2) * 64, hi, lo);
            }
        } else {            // MODE 2 (shortcut, C=32): one group per h
            const float* F = (const float*)Fv;
            int b = gm >> 10, n = gm & 1023;
            __nv_bfloat16 hi[16], lo[16];
            #pragma unroll
            for (int j = 0; j < 16; j++) {
                int c = h * 16 + j;
                float v = F[(size_t)(b * CIN + c) * NN + n];
                int pi = pidx(j);
                split2(v, hi[pi], lo[pi]);
            }
            st64i(rowp + h * 64, hi, lo);
        }
    }

    // ---- phase 3: hoist W fragments from global table (cached) ----
    int cg = wid & 3, mh = wid >> 2;
    int no = cg * 16;
    int g = lane >> 2, p = lane & 3;
    uint2 A02[NG], A13[NG];
    #pragma unroll
    for (int s = 0; s < NG; s++) {
        A02[s] = *(const uint2*)(Wx + (no + g) * (NG * 16) + s * 16 + p * 4);
        A13[s] = *(const uint2*)(Wx + (no + g + 8) * (NG * 16) + s * 16 + p * 4);
    }
    __syncthreads();

    // ---- phase 4: mma main loop (1 LDS.128 per group -> 3 mma) ----
    float sA = 0.f, qA = 0.f, sB = 0.f, qB = 0.f;
    float accs[8][4];
    #pragma unroll
    for (int ch = 0; ch < 8; ch++) {
        int m0 = mh * 64 + ch * 8;
        const char* brow = Xs + (m0 + g) * ROWB + p * 16;
        float d0 = 0.f, d1 = 0.f, d2 = 0.f, d3 = 0.f;
        #pragma unroll
        for (int s = 0; s < S16; s++) {
            uint4 bv = *(const uint4*)(brow + s * 64);
            mma16816(d0, d1, d2, d3, A02[s].x, A13[s].x, A02[s].y, A13[s].y, bv.x, bv.y);
            mma16816(d0, d1, d2, d3, A02[s].x, A13[s].x, A02[s].y, A13[s].y, bv.z, bv.w);
            mma16816(d0, d1, d2, d3, A02[S16 + s].x, A13[S16 + s].x,
                     A02[S16 + s].y, A13[S16 + s].y, bv.x, bv.y);
        }
        accs[ch][0] = d0; accs[ch][1] = d1; accs[ch][2] = d2; accs[ch][3] = d3;
        sA += d0 + d1;  qA += d0 * d0 + d1 * d1;
        sB += d2 + d3;  qB += d2 * d2 + d3 * d3;
    }

    // ---- stores ----
    if (MODE == 2) {
        float* Sout = (float*)Soutv;
        float* outA = Sout + (size_t)(no + g) * Mtot + gm0 + mh * 64 + 2 * p;
        float* outB = Sout + (size_t)(no + g + 8) * Mtot + gm0 + mh * 64 + 2 * p;
        #pragma unroll
        for (int ch = 0; ch < 8; ch++) {
            *(float2*)(outA + ch * 8) = make_float2(accs[ch][0], accs[ch][1]);
            *(float2*)(outB + ch * 8) = make_float2(accs[ch][2], accs[ch][3]);
        }
    } else {
        __half* Sout = (__half*)Soutv;
        __half* outA = Sout + (size_t)(no + g) * Mtot + gm0 + mh * 64 + 2 * p;
        __half* outB = Sout + (size_t)(no + g + 8) * Mtot + gm0 + mh * 64 + 2 * p;
        #pragma unroll
        for (int ch = 0; ch < 8; ch++) {
            __half2 pa = __floats2half2_rn(accs[ch][0], accs[ch][1]);
            __half2 pb = __floats2half2_rn(accs[ch][2], accs[ch][3]);
            *(__half2*)(outA + ch * 8) = pa;
            *(__half2*)(outB + ch * 8) = pb;
        }
    }

    // ---- phase 5: stats reduction (quad -> smem -> global) ----
    #pragma unroll
    for (int off = 1; off <= 2; off <<= 1) {
        sA += __shfl_xor_sync(0xffffffffu, sA, off);
        qA += __shfl_xor_sync(0xffffffffu, qA, off);
        sB += __shfl_xor_sync(0xffffffffu, sB, off);
        qB += __shfl_xor_sync(0xffffffffu, qB, off);
    }
    if (p == 0) {
        atomicAdd(&sred[no + g], sA);
        atomicAdd(&sred[64 + no + g], qA);
        atomicAdd(&sred[no + g + 8], sB);
        atomicAdd(&sred[64 + no + g + 8], qB);
    }
    __syncthreads();
    if (tid < 64)        atomicAdd(&g_sum[statsIdx][tid], sred[tid]);
    else if (tid < 128)  atomicAdd(&g_sqsum[statsIdx][tid - 64], sred[tid]);
}

// layer0 + shortcut in one launch: blocks 0-255 shortcut, 256+ layer 0
__global__ __launch_bounds__(256, 3) void k_gemm0sc(
    const uint16_t* __restrict__ Wx0, const uint16_t* __restrict__ WxSC,
    const float* __restrict__ F, const float* __restrict__ FT,
    __half* __restrict__ S0, float* __restrict__ SC)
{
    extern __shared__ __align__(16) char sm[];
    if (blockIdx.x < M_SC / 128)
        gemm_body<32, 2>(WxSC, F, SC, 3, 0, M_SC, blockIdx.x, sm);
    else
        gemm_body<68, 0>(Wx0, FT, S0, 0, 0, M_ALL, blockIdx.x - M_SC / 128, sm);
}

template<int C, int MODE>
__global__ __launch_bounds__(256, 3) void k_gemm(
    const uint16_t* __restrict__ Wx,
    const void* __restrict__ F,
    void* __restrict__ Sout,
    int statsIdx, int prevIdx, int Mtot)
{
    extern __shared__ __align__(16) char sm[];
    gemm_body<C, MODE>(Wx, F, Sout, statsIdx, prevIdx, Mtot, blockIdx.x, sm);
}

// ------------------------------ finalize BN ---------------------------------
__global__ void k_finalize(const float* __restrict__ gamma,
                           const float* __restrict__ beta,
                           int idx, float invM) {
    int o = threadIdx.x;
    if (o < O0) {
        float m = g_sum[idx][o] * invM;
        float v = g_sqsum[idx][o] * invM - m * m;
        float a = gamma[o] / sqrtf(v + BN_EPS);
        g_a[idx][o] = a;
        g_c[idx][o] = beta[o] - m * a;
    }
}

// merged finalize for idx 2 (tid<64) and idx 3 (tid>=64)
__global__ void k_finalize23(const float* __restrict__ g2, const float* __restrict__ b2,
                             const float* __restrict__ g3, const float* __restrict__ b3) {
    int t = threadIdx.x;
    int idx = (t < 64) ? 2 : 3;
    int o = t & 63;
    float invM = (t < 64) ? (1.f / (float)M_ALL) : (1.f / (float)M_SC);
    const float* gg = (t < 64) ? g2 : g3;
    const float* bb = (t < 64) ? b2 : b3;
    float m = g_sum[idx][o] * invM;
    float v = g_sqsum[idx][o] * invM - m * m;
    float a = gg[o] / sqrtf(v + BN_EPS);
    g_a[idx][o] = a;
    g_c[idx][o] = bb[o] - m * a;
}

// ------------------------------ final fuse ----------------------------------
__global__ void k_final(const __half* __restrict__ S2,
                        float* __restrict__ out) {
    int t = blockIdx.x * blockDim.x + threadIdx.x;
    if (t >= BB * O0 * NN) return;
    int n = t & (NN - 1);
    int o = (t >> 10) & 63;
    int b = t >> 16;
    float a2 = g_a[2][o], c2 = g_c[2][o];
    const __half2* S = (const __half2*)(S2 + (size_t)o * M_ALL + b * (NN * KK) + n * KK);
    float s = 0.f;
    #pragma unroll
    for (int q = 0; q < 8; q++) {
        float2 v = __half22float2(S[q]);
        s += fmaxf(fmaf(a2, v.x, c2), 0.f) + fmaxf(fmaf(a2, v.y, c2), 0.f);
    }
    float fts = s * (1.f / KK);
    float sc = g_scb[(size_t)o * M_SC + b * NN + n];
    float v = fmaf(g_a[3][o], sc, g_c[3][o]) + fts;
    out[t] = fmaxf(v, 0.f);
}

// ------------------------------- launch -------------------------------------
extern "C" void kernel_launch(void* const* d_in, const int* in_sizes, int n_in,
                              void* d_out, int out_size) {
    const float* points    = (const float*)d_in[0];
    const float* features  = (const float*)d_in[1];
    const int*   edge_list = (const int*)d_in[2];
    const float* edge_feat = (const float*)d_in[3];
    int base = (n_in >= 17 && in_sizes[4] == 1) ? 5 : 4;
    const float* W0   = (const float*)d_in[base + 0];
    const float* W1   = (const float*)d_in[base + 1];
    const float* W2   = (const float*)d_in[base + 2];
    const float* g0   = (const float*)d_in[base + 3];
    const float* b0   = (const float*)d_in[base + 4];
    const float* g1   = (const float*)d_in[base + 5];
    const float* b1   = (const float*)d_in[base + 6];
    const float* g2   = (const float*)d_in[base + 7];
    const float* b2   = (const float*)d_in[base + 8];
    const float* sc_w = (const float*)d_in[base + 9];
    const float* sc_g = (const float*)d_in[base + 10];
    const float* sc_b = (const float*)d_in[base + 11];

    void *pS0, *pS1, *pSC, *pW0, *pW1, *pW2, *pWS, *pFT;
    cudaGetSymbolAddress(&pS0, g_S0);
    cudaGetSymbolAddress(&pS1, g_S1);
    cudaGetSymbolAddress(&pSC, g_scb);
    cudaGetSymbolAddress(&pW0, g_wx0);
    cudaGetSymbolAddress(&pW1, g_wx1);
    cudaGetSymbolAddress(&pW2, g_wx2);
    cudaGetSymbolAddress(&pWS, g_wxsc);
    cudaGetSymbolAddress(&pFT, g_featT);
    __half* S0 = (__half*)pS0;
    __half* S1 = (__half*)pS1;
    float* SC = (float*)pSC;

    // smem: 1024 ctrl + Xs (ROWB: layer0 320, layer1/2 320, shortcut 192)
    const int smem0  = 1024 + 128 * 320;   // 41984 (covers shortcut too)
    const int smem1  = 1024 + 128 * 320;   // 41984
    cudaFuncSetAttribute(k_gemm0sc, cudaFuncAttributeMaxDynamicSharedMemorySize, smem0);
    cudaFuncSetAttribute(k_gemm<64, 1>, cudaFuncAttributeMaxDynamicSharedMemorySize, smem1);

    // prep grid: 4 wext + 1024 transpose tiles + 512 init blocks
    k_prep<<<4 + BB * (NN / 32) + 512, 256>>>(W0, W1, W2, sc_w, features);
    k_scatter<<<(BB * PP + 255) / 256, 256>>>(edge_list, edge_feat);
    k_knn2<<<BB * NN / 8, 256>>>(points);

    k_gemm0sc<<<M_SC / 128 + M_ALL / 128, 256, smem0>>>(
        (const uint16_t*)pW0, (const uint16_t*)pWS, features, (const float*)pFT, S0, SC);
    k_finalize<<<1, 64>>>(g0, b0, 0, 1.f / (float)M_ALL);
    k_gemm<64, 1><<<M_ALL / 128, 256, smem1>>>((const uint16_t*)pW1, S0, S1, 1, 0, M_ALL);
    k_finalize<<<1, 64>>>(g1, b1, 1, 1.f / (float)M_ALL);
    k_gemm<64, 1><<<M_ALL / 128, 256, smem1>>>((const uint16_t*)pW2, S1, S0, 2, 1, M_ALL);
    k_finalize23<<<1, 128>>>(g2, b2, sc_g, sc_b);

    k_final<<<(BB * O0 * NN + 255) / 256, 256>>>(S0, (float*)d_out);
}